// round 3
// baseline (speedup 1.0000x reference)
#include <cuda_runtime.h>
#include <cstdint>

#define Bb 2
#define Cc 66
#define Tt 32
#define Nn 512
#define TNc (Tt*Nn)          // 16384
#define BTNc (Bb*TNc)        // 32768
#define Ll 2
#define QKd 64
#define Vdim 124
#define Kn 16

// ---------------- device scratch (no cudaMalloc allowed) ----------------
static __device__ float g_proj[33554432];     // [BTN][1024]  (134 MB)
static __device__ int   g_nid[BTNc * Kn];     // neighbor global point ids
static __device__ float g_wcombT[64 * 1024];  // [c][row] transposed combined weights
static __device__ float g_bias[1024];
static __device__ float g_wpos[2 * 256 * 4];  // [l][row(252 pad 256)][4]

// Row layout (per point, stride 1024):
//   l*512 + 0   .. 251 : center proj (q 0..63 | k 64..127 | v 128..251)  (+bias)
//   l*512 + 256 .. 507 : neighbor proj (same order, no bias)

// ---------------- K0: weight prep ----------------
__global__ __launch_bounds__(256) void prep_kernel(
        const float* __restrict__ Wqk, const float* __restrict__ bqk,
        const float* __restrict__ Wv,  const float* __restrict__ bv) {
    int i = blockIdx.x * blockDim.x + threadIdx.x;   // 0 .. 65535
    // wcombT
    {
        int c = i >> 10, r = i & 1023;
        int l = r >> 9, within = r & 511, typ = within >> 8, o = within & 255;
        float w = 0.f;
        if (o < 252 && c < 62) {
            int col = (typ == 0 ? 4 : 66) + c;
            if (o < 128) w = Wqk[(l * 128 + o) * 128 + col];
            else         w = Wv[(l * 124 + (o - 128)) * 128 + col];
        }
        g_wcombT[c * 1024 + r] = w;
    }
    if (i < 1024) {
        int r = i, l = r >> 9, within = r & 511, typ = within >> 8, o = within & 255;
        float bb = 0.f;
        if (typ == 0 && o < 252) bb = (o < 128) ? bqk[l * 128 + o] : bv[l * 124 + (o - 128)];
        g_bias[r] = bb;
    }
    if (i < 2048) {
        int l = i >> 10, rem = i & 1023, o = rem >> 2, j = rem & 3;
        float w = 0.f;
        if (o < 128)      w = Wqk[(l * 128 + o) * 128 + j];
        else if (o < 252) w = Wv[(l * 124 + (o - 128)) * 128 + j];
        g_wpos[i] = w;
    }
}

// ---------------- K1: kNN (top-16 by (dist2, pool_idx)) ----------------
__global__ __launch_bounds__(128) void knn_kernel(const float* __restrict__ x) {
    int blk = blockIdx.x;
    int bt = blk >> 2, quarter = blk & 3;
    int b = bt / Tt, t = bt % Tt;
    int n = quarter * 128 + threadIdx.x;

    __shared__ float cx_[1536], cy_[1536], cz_[1536];
    const float* xb = x + (size_t)b * Cc * TNc;
    for (int idx = threadIdx.x; idx < 1536; idx += 128) {
        int s = idx >> 9, j = idx & 511;
        int tp = t - 1 + s; tp = tp < 0 ? 0 : (tp > Tt - 1 ? Tt - 1 : tp);
        cx_[idx] = xb[0 * TNc + tp * Nn + j];
        cy_[idx] = xb[1 * TNc + tp * Nn + j];
        cz_[idx] = xb[2 * TNc + tp * Nn + j];
    }
    __syncthreads();

    float px = xb[0 * TNc + t * Nn + n];
    float py = xb[1 * TNc + t * Nn + n];
    float pz = xb[2 * TNc + t * Nn + n];

    // Sentinel: distance field = +inf bits (0x7F800000) so that
    //  (a) thresh derived from key[15] stays +inf while empty slots remain,
    //  (b) every finite dist2 (bits < 0x7F800000, sign bit 0) beats a sentinel.
    unsigned long long key[16];
#pragma unroll
    for (int i = 0; i < 16; i++) key[i] = 0x7F800000FFFFFFFFull;
    float thresh = __uint_as_float(0x7F800000u);  // +inf

    for (int j = 0; j < 1536; j++) {
        float dx = px - cx_[j];
        float dy = py - cy_[j];
        float dz = pz - cz_[j];
        // match XLA: separate mults, sequential adds, no FMA contraction
        float d = __fadd_rn(__fadd_rn(__fmul_rn(dx, dx), __fmul_rn(dy, dy)), __fmul_rn(dz, dz));
        if (d <= thresh) {
            unsigned long long kk = ((unsigned long long)__float_as_uint(d) << 32) | (unsigned)j;
            if (kk < key[15]) {
                key[15] = kk;
#pragma unroll
                for (int m = 15; m > 0; m--) {
                    unsigned long long a = key[m - 1], c2 = key[m];
                    if (c2 < a) { key[m - 1] = c2; key[m] = a; }
                }
                thresh = __uint_as_float((unsigned)(key[15] >> 32));
            }
        }
    }
    int p = bt * Nn + n;
#pragma unroll
    for (int i = 0; i < 16; i++) {
        int pj = (int)(key[i] & 0xFFFFFFFFu);
        int s = pj >> 9, jn = pj & 511;
        int tp = t - 1 + s; tp = tp < 0 ? 0 : (tp > Tt - 1 ? Tt - 1 : tp);
        g_nid[p * Kn + i] = (b * Tt + tp) * Nn + jn;
    }
}

// ---------------- K2: projection GEMM (1008x62) @ (62 x 32768) ----------------
__global__ __launch_bounds__(256) void proj_kernel(const float* __restrict__ x) {
    __shared__ __align__(16) float Xs[62][128];
    int p0 = blockIdx.x * 128;
    int b = p0 / TNc, rem0 = p0 % TNc;
    const float* xb = x + ((size_t)b * Cc + 4) * TNc + rem0;
    for (int idx = threadIdx.x; idx < 62 * 128; idx += 256) {
        int c = idx >> 7, pp = idx & 127;
        Xs[c][pp] = xb[(size_t)c * TNc + pp];
    }
    __syncthreads();

    int tx = threadIdx.x & 31, ty = threadIdx.x >> 5;
    float* outBase = g_proj + (size_t)(p0 + tx * 4) * 1024;

    for (int chunk = 0; chunk < 16; chunk++) {
        int r0 = ty * 128 + chunk * 8;
        float acc[8][4];
#pragma unroll
        for (int rr = 0; rr < 8; rr++) {
            float bb = g_bias[r0 + rr];
#pragma unroll
            for (int pp = 0; pp < 4; pp++) acc[rr][pp] = bb;
        }
#pragma unroll 2
        for (int c = 0; c < 62; c++) {
            const float4 xv = *(const float4*)&Xs[c][tx * 4];
            const float4 wa = *(const float4*)&g_wcombT[c * 1024 + r0];
            const float4 wb = *(const float4*)&g_wcombT[c * 1024 + r0 + 4];
            float wv[8] = {wa.x, wa.y, wa.z, wa.w, wb.x, wb.y, wb.z, wb.w};
            float xvv[4] = {xv.x, xv.y, xv.z, xv.w};
#pragma unroll
            for (int rr = 0; rr < 8; rr++)
#pragma unroll
                for (int pp = 0; pp < 4; pp++)
                    acc[rr][pp] = fmaf(wv[rr], xvv[pp], acc[rr][pp]);
        }
#pragma unroll
        for (int pp = 0; pp < 4; pp++) {
            float* dst = outBase + (size_t)pp * 1024 + r0;
            *(float4*)dst       = make_float4(acc[0][pp], acc[1][pp], acc[2][pp], acc[3][pp]);
            *(float4*)(dst + 4) = make_float4(acc[4][pp], acc[5][pp], acc[6][pp], acc[7][pp]);
        }
    }
}

// ---------------- K3: attention ----------------
#define QSTR 260
__global__ __launch_bounds__(256) void attn_kernel(const float* __restrict__ x,
                                                   float* __restrict__ out) {
    __shared__ __align__(16) float qkvS[16 * QSTR];
    __shared__ __align__(16) float ctrS[256];
    __shared__ __align__(16) float wposS[2 * 256 * 4];
    __shared__ float deltaS[16][4];
    __shared__ int   nidS[16];
    __shared__ float eS[16][16];
    __shared__ float afS[16];
    __shared__ float outS[16][128];

    int tid = threadIdx.x;
    int p0 = blockIdx.x * 16;
    int b = p0 / TNc, rem0 = p0 % TNc;

    for (int i = tid; i < 2048; i += 256) wposS[i] = g_wpos[i];
    __syncthreads();

    for (int l = 0; l < Ll; l++) {
        for (int pt = 0; pt < 16; pt++) {
            int p = p0 + pt;
            if (tid < 252) ctrS[tid] = g_proj[(size_t)p * 1024 + l * 512 + tid];
            if (tid < 16) {
                int g = g_nid[p * Kn + tid];
                nidS[tid] = g;
                int grem = g - b * TNc;
#pragma unroll
                for (int cc = 0; cc < 4; cc++) {
                    float cp = x[((size_t)b * Cc + cc) * TNc + rem0 + pt];
                    float np = x[((size_t)b * Cc + cc) * TNc + grem];
                    deltaS[tid][cc] = cp - np;
                }
            }
            if (tid < 4) outS[pt][tid] = x[((size_t)b * Cc + tid) * TNc + rem0 + pt];
            __syncthreads();

            // assemble q/k/v: element (i, c)
            {
                int i = tid >> 4, cb = tid & 15;
                float d0 = deltaS[i][0], d1 = deltaS[i][1], d2 = deltaS[i][2], d3 = deltaS[i][3];
                const float* nb = g_proj + (size_t)nidS[i] * 1024 + l * 512 + 256;
                const float* wp = wposS + l * 1024;
#pragma unroll
                for (int s2 = 0; s2 < 16; s2++) {
                    int c = cb + (s2 << 4);
                    if (c < 252) {
                        float4 w4 = *(const float4*)&wp[c * 4];
                        float v = nb[c] + ctrS[c] + w4.x * d0 + w4.y * d1 + w4.z * d2 + w4.w * d3;
                        qkvS[i * QSTR + c] = v;
                    }
                }
            }
            __syncthreads();

            // energy: 256 threads, one (i,j) each
            {
                int ii = tid >> 4, jj = tid & 15;
                const float* qi = qkvS + ii * QSTR;
                const float* kj = qkvS + jj * QSTR + 64;
                float s = 0.f;
#pragma unroll
                for (int c = 0; c < 64; c += 4) {
                    float4 a = *(const float4*)&qi[c];
                    float4 b4 = *(const float4*)&kj[c];
                    s += a.x * b4.x + a.y * b4.y + a.z * b4.z + a.w * b4.w;
                }
                eS[ii][jj] = s * 0.125f;   // / sqrt(64)
            }
            __syncthreads();

            if (tid < 16) {
                float m = -1e30f;
#pragma unroll
                for (int j = 0; j < 16; j++) m = fmaxf(m, eS[tid][j]);
                float sum = 0.f;
#pragma unroll
                for (int j = 0; j < 16; j++) sum += __expf(eS[tid][j] - m);
                afS[tid] = __expf(eS[tid][0] - m) / sum;
            }
            __syncthreads();

            if (tid < 124) {
                float s = 0.f;
#pragma unroll
                for (int i = 0; i < 16; i++) s += afS[i] * qkvS[i * QSTR + 128 + tid];
                outS[pt][4 + tid] = s;
            }
            __syncthreads();
        }
        // coalesced write of this layer's 16 points
        for (int idx = tid; idx < 2048; idx += 256) {
            int c = idx >> 4, pt = idx & 15;
            out[((size_t)(l * Bb + b) * 128 + c) * TNc + rem0 + pt] = outS[pt][c];
        }
        __syncthreads();
    }
}

// ---------------- launch ----------------
extern "C" void kernel_launch(void* const* d_in, const int* in_sizes, int n_in,
                              void* d_out, int out_size) {
    const float* x   = (const float*)d_in[0];
    const float* Wqk = (const float*)d_in[1];
    const float* bqk = (const float*)d_in[2];
    const float* Wv  = (const float*)d_in[3];
    const float* bv  = (const float*)d_in[4];
    float* out = (float*)d_out;

    prep_kernel<<<256, 256>>>(Wqk, bqk, Wv, bv);
    knn_kernel<<<Bb * Tt * 4, 128>>>(x);
    proj_kernel<<<BTNc / 128, 256>>>(x);
    attn_kernel<<<BTNc / 16, 256>>>(x, out);
}